// round 4
// baseline (speedup 1.0000x reference)
#include <cuda_runtime.h>
#include <cstdint>

// ============================================================================
// Monte-Carlo E[softmax(mean + eps)], JAX threefry-partitionable bit-exact.
// R4: software-pipelined row reduction (acc-update of sample s fused into the
//     eval loop of sample s+1 -> SHFL-butterfly latency hidden under threefry);
//     exact I2F mantissa path; ww recentering folded; ms as float4 / LDS.128.
// ============================================================================

#define NROWS 16384
#define NCOLS 512
#define WARPS_PER_BLOCK 8
#define NTHREADS (WARPS_PER_BLOCK * 32)
#define KPL 16
#define MAX_SAMPLES 512

__device__ __forceinline__ uint32_t madd(uint32_t a, uint32_t b, uint32_t one) {
    uint32_t t;
    asm("mad.lo.u32 %0, %1, %2, %3;" : "=r"(t) : "r"(a), "r"(one), "r"(b));
    return t;
}

// Compile-time threefry for per-sample subkeys (amortized, per block).
__device__ __forceinline__ void tf_round_c(uint32_t& x0, uint32_t& x1, int r) {
    x0 += x1;
    x1 = __funnelshift_l(x1, x1, r);
    x1 ^= x0;
}
__device__ __forceinline__ uint2 threefry2x32_c(uint32_t k0, uint32_t k1,
                                                uint32_t c0, uint32_t c1) {
    uint32_t k2 = k0 ^ k1 ^ 0x1BD11BDAu;
    uint32_t x0 = c0 + k0;
    uint32_t x1 = c1 + k1;
    tf_round_c(x0,x1,13); tf_round_c(x0,x1,15); tf_round_c(x0,x1,26); tf_round_c(x0,x1,6);
    x0 += k1; x1 += k2 + 1u;
    tf_round_c(x0,x1,17); tf_round_c(x0,x1,29); tf_round_c(x0,x1,16); tf_round_c(x0,x1,24);
    x0 += k2; x1 += k0 + 2u;
    tf_round_c(x0,x1,13); tf_round_c(x0,x1,15); tf_round_c(x0,x1,26); tf_round_c(x0,x1,6);
    x0 += k0; x1 += k1 + 3u;
    tf_round_c(x0,x1,17); tf_round_c(x0,x1,29); tf_round_c(x0,x1,16); tf_round_c(x0,x1,24);
    x0 += k1; x1 += k2 + 4u;
    tf_round_c(x0,x1,13); tf_round_c(x0,x1,15); tf_round_c(x0,x1,26); tf_round_c(x0,x1,6);
    x0 += k2; x1 += k0 + 5u;
    return make_uint2(x0, x1);
}

// Hot fold: counter (0, c1); x1 passed pre-added (c1 + k1); returns x0^x1.
// Adds on IMAD (fma pipe) via opaque `one`; SHF+LOP3 stay on alu pipe.
#define TFR(r) { x0 = madd(x1, x0, one); \
                 x1 = __funnelshift_l(x1, x1, r) ^ x0; }
__device__ __forceinline__ uint32_t tf_fold(
    uint32_t k0, uint32_t k1, uint32_t k2,
    uint32_t i1, uint32_t i2, uint32_t i3, uint32_t i4, uint32_t i5,
    uint32_t x1, uint32_t one)
{
    uint32_t x0 = k0;
    TFR(13); TFR(15); TFR(26); TFR(6);
    x0 = madd(k1, x0, one); x1 = madd(i1, x1, one);   // i1 = k2+1
    TFR(17); TFR(29); TFR(16); TFR(24);
    x0 = madd(k2, x0, one); x1 = madd(i2, x1, one);   // i2 = k0+2
    TFR(13); TFR(15); TFR(26); TFR(6);
    x0 = madd(k0, x0, one); x1 = madd(i3, x1, one);   // i3 = k1+3
    TFR(17); TFR(29); TFR(16); TFR(24);
    x0 = madd(k1, x0, one); x1 = madd(i4, x1, one);   // i4 = k2+4
    TFR(13); TFR(15); TFR(26); TFR(6);
    x0 = madd(k2, x0, one); x1 = madd(i5, x1, one);   // i5 = k0+5
    return x0 ^ x1;
}

// One element eval: threefry bits -> uniform -> erfinv -> exp2 value.
__device__ __forceinline__ float eval_one(
    uint32_t k0, uint32_t k1, uint32_t k2,
    uint32_t i1, uint32_t i2, uint32_t i3, uint32_t i4, uint32_t i5,
    uint32_t x1init, uint32_t one, float m2v, float s3v)
{
    const float LO = __int_as_float(0xBF7FFFFF);  // nextafter(-1, 0)
    uint32_t bits = tf_fold(k0, k1, k2, i1, i2, i3, i4, i5, x1init, one);
    // m = bits >> 9 (fma pipe); exact I2F; u = m*2^-22 + LO (single rounding,
    // bit-identical to XLA's ((m|1.0f)-1)*2+LO path).
    float mf = (float)__umulhi(bits, 0x00800000u);
    float u = fmaf(mf, 0x1p-22f, LO);
    // XLA ErfInv (Giles), main branch; rare tail overwrites.
    float t = fmaf(-u, u, 1.0f);
    float lg;
    asm("lg2.approx.f32 %0, %1;" : "=f"(lg) : "f"(t));
    // ww = -ln2*lg - 2.5 in one FFMA
    float ww = fmaf(lg, -0.6931471805599453f, -2.5f);
    float p = 2.81022636e-08f;
    p = fmaf(p, ww, 3.43273939e-07f);
    p = fmaf(p, ww, -3.5233877e-06f);
    p = fmaf(p, ww, -4.39150654e-06f);
    p = fmaf(p, ww, 0.00021858087f);
    p = fmaf(p, ww, -0.00125372503f);
    p = fmaf(p, ww, -0.00417768164f);
    p = fmaf(p, ww, 0.246640727f);
    p = fmaf(p, ww, 1.50140941f);
    if (__builtin_expect(!!(lg <= -7.2134752044448170f), 0)) {  // w >= 5
        float w = lg * -0.6931471805599453f;
        float sw;
        asm("sqrt.approx.f32 %0, %1;" : "=f"(sw) : "f"(w));
        float v = sw - 3.0f;
        p = -0.000200214257f;
        p = fmaf(p, v, 0.000100950558f);
        p = fmaf(p, v, 0.00134934322f);
        p = fmaf(p, v, -0.00367342844f);
        p = fmaf(p, v, 0.00573950773f);
        p = fmaf(p, v, -0.0076224613f);
        p = fmaf(p, v, 0.00943887047f);
        p = fmaf(p, v, 1.00167406f);
        p = fmaf(p, v, 2.83297682f);
    }
    float g = p * u;                 // erfinv(u)
    float tt = fmaf(g, s3v, m2v);    // (mean + eps) * log2(e)
    float ev;
    asm("ex2.approx.f32 %0, %1;" : "=f"(ev) : "f"(tt));
    return ev;
}

__device__ __forceinline__ float butterfly_rcp(float part) {
#pragma unroll
    for (int o = 16; o > 0; o >>= 1)
        part += __shfl_xor_sync(0xffffffffu, part, o);
    float rinv;
    asm("rcp.approx.f32 %0, %1;" : "=f"(rinv) : "f"(part));
    return rinv;
}

__global__ void __launch_bounds__(NTHREADS, 4)
mc_softmax_kernel(const float* __restrict__ mean,
                  const float* __restrict__ var,
                  const int* __restrict__ d_ns,
                  float* __restrict__ out,
                  uint32_t one) {
    // (m2_{2j}, m2_{2j+1}, s3_{2j}, s3_{2j+1}) per thread -> one LDS.128/pair.
    __shared__ float4 ms4[(KPL / 2) * NTHREADS];  // 32 KB
    __shared__ uint2 skeys[MAX_SAMPLES];          //  4 KB

    int ns = d_ns ? *d_ns : 400;
    if (ns > MAX_SAMPLES) ns = MAX_SAMPLES;

    int tid = threadIdx.x;
    for (int s = tid; s < ns; s += NTHREADS)
        skeys[s] = threefry2x32_c(0u, 42u, 0u, (uint32_t)s);

    int warp = tid >> 5;
    int lane = tid & 31;
    int row = blockIdx.x * WARPS_PER_BLOCK + warp;
    int base = row * NCOLS + lane;

    const float LOG2E = 1.4426950408889634f;
    const float S2LOG2E = 1.41421356237309504880f * 1.4426950408889634f;

    float acc[KPL];
#pragma unroll
    for (int j = 0; j < KPL / 2; j++) {
        int ia = base + 32 * (2 * j);
        int ib = base + 32 * (2 * j + 1);
        float4 v;
        v.x = mean[ia] * LOG2E;
        v.y = mean[ib] * LOG2E;
        v.z = sqrtf(var[ia]) * S2LOG2E;
        v.w = sqrtf(var[ib]) * S2LOG2E;
        ms4[j * NTHREADS + tid] = v;
        acc[2 * j] = 0.0f;
        acc[2 * j + 1] = 0.0f;
    }
    __syncthreads();

    float e[KPL];
    float rinv;

    // ---- prologue: sample 0 ----
    {
        uint2 key = skeys[0];
        uint32_t k0 = key.x, k1 = key.y;
        uint32_t k2 = k0 ^ k1 ^ 0x1BD11BDAu;
        uint32_t i1 = k2 + 1u, i2 = k0 + 2u, i3 = k1 + 3u,
                 i4 = k2 + 4u, i5 = k0 + 5u;
        uint32_t cb = (uint32_t)base + k1;
        float part = 0.0f;
#pragma unroll
        for (int j = 0; j < KPL / 2; j++) {
            float4 msk = ms4[j * NTHREADS + tid];
            float ea = eval_one(k0, k1, k2, i1, i2, i3, i4, i5,
                                cb + 32u * (uint32_t)(2 * j), one, msk.x, msk.z);
            float eb = eval_one(k0, k1, k2, i1, i2, i3, i4, i5,
                                cb + 32u * (uint32_t)(2 * j + 1), one, msk.y, msk.w);
            e[2 * j] = ea;
            e[2 * j + 1] = eb;
            part += ea;
            part += eb;
        }
        rinv = butterfly_rcp(part);
    }

    // ---- pipelined main loop: eval sample s while retiring sample s-1 ----
    for (int s = 1; s < ns; s++) {
        uint2 key = skeys[s];
        uint32_t k0 = key.x, k1 = key.y;
        uint32_t k2 = k0 ^ k1 ^ 0x1BD11BDAu;
        uint32_t i1 = k2 + 1u, i2 = k0 + 2u, i3 = k1 + 3u,
                 i4 = k2 + 4u, i5 = k0 + 5u;
        uint32_t cb = (uint32_t)base + k1;
        float part = 0.0f;
#pragma unroll
        for (int j = 0; j < KPL / 2; j++) {
            float4 msk = ms4[j * NTHREADS + tid];
            float ea = eval_one(k0, k1, k2, i1, i2, i3, i4, i5,
                                cb + 32u * (uint32_t)(2 * j), one, msk.x, msk.z);
            float eb = eval_one(k0, k1, k2, i1, i2, i3, i4, i5,
                                cb + 32u * (uint32_t)(2 * j + 1), one, msk.y, msk.w);
            // retire previous sample (acc uses OLD e + rinv), then rotate.
            acc[2 * j] = fmaf(e[2 * j], rinv, acc[2 * j]);
            acc[2 * j + 1] = fmaf(e[2 * j + 1], rinv, acc[2 * j + 1]);
            e[2 * j] = ea;
            e[2 * j + 1] = eb;
            part += ea;
            part += eb;
        }
        rinv = butterfly_rcp(part);
    }

    // ---- epilogue: retire last sample, write out ----
    float inv = 1.0f / (float)ns;
#pragma unroll
    for (int k = 0; k < KPL; k++) {
        acc[k] = fmaf(e[k], rinv, acc[k]);
        out[base + 32 * k] = acc[k] * inv;
    }
}

extern "C" void kernel_launch(void* const* d_in, const int* in_sizes, int n_in,
                              void* d_out, int out_size) {
    const float* mean = (const float*)d_in[0];
    const float* var = (const float*)d_in[1];
    const int* ns = (n_in >= 3) ? (const int*)d_in[2] : nullptr;
    float* out = (float*)d_out;

    dim3 grid(NROWS / WARPS_PER_BLOCK);
    dim3 block(NTHREADS);
    mc_softmax_kernel<<<grid, block>>>(mean, var, ns, out, 1u);
}